// round 8
// baseline (speedup 1.0000x reference)
#include <cuda_runtime.h>
#include <cuda_bf16.h>
#include <cstdint>
#include <math.h>

#define B_    32
#define T_    512
#define D_    300
#define U_    300
#define NG_   1200       // 4*U
#define ZPAD  1216       // padded zx row stride
#define M_    16384      // B*T

// ---- clustered recurrence tiling ----
#define CL    8          // CTAs per cluster (unit groups)
#define NUc   38         // units per CTA (8*38=304, last CTA masked)
#define NCOLc 152        // 4*NUc gate columns per CTA
#define BGc   4          // batches per CTA
#define NBG   8          // batch groups (8*4 = 32)
#define KCHc  5          // k chunks
#define KCc   60         // k per chunk (5*60=300), 30 k-pairs
#define RTc   768        // threads (760 mm-active)

typedef unsigned long long ULL;

// ------------------- static device scratch (no allocs allowed) -------------
__device__ __align__(16) float g_zx[2][M_][ZPAD];     // x@Wk+b per dir
__device__ __align__(16) float g_hs[2][B_][T_][U_];   // h history per dir

// ------------------- helpers ----------------------------------------------
union UF2 { float2 f; ULL u; };
__device__ __forceinline__ ULL pack2(float a, float b) {
    UF2 x; x.f = make_float2(a, b); return x.u;
}
__device__ __forceinline__ float2 unpack2(ULL v) {
    UF2 x; x.u = v; return x.f;
}
__device__ __forceinline__ void ffma2(ULL& d, ULL a, ULL b) {
    asm("fma.rn.f32x2 %0, %1, %2, %0;" : "+l"(d) : "l"(a), "l"(b));
}
__device__ __forceinline__ float sigm(float x) { return 1.f / (1.f + __expf(-x)); }
__device__ __forceinline__ uint32_t smem_u32(const void* p) {
    uint32_t a;
    asm("{ .reg .u64 t; cvta.to.shared.u64 t, %1; cvt.u32.u64 %0, t; }" : "=r"(a) : "l"(p));
    return a;
}
__device__ __forceinline__ void st_cluster_f32(uint32_t laddr, int rank, float v) {
    uint32_t ra;
    asm volatile("mapa.shared::cluster.u32 %0, %1, %2;" : "=r"(ra) : "r"(laddr), "r"(rank));
    asm volatile("st.shared::cluster.f32 [%0], %1;" :: "r"(ra), "f"(v) : "memory");
}
__device__ __forceinline__ void cluster_sync_() {
    asm volatile("barrier.cluster.arrive.aligned;" ::: "memory");
    asm volatile("barrier.cluster.wait.aligned;" ::: "memory");
}

// ------------------- kernel 1: zx = gather(emb) @ Wk + b -------------------
// (unchanged from round 7: 590us, fma 53%) BM=128, BN=64, BK=16, 256 thr.
#define GKT 19   // ceil(304/16)

__global__ void __launch_bounds__(256, 2) gemm_zx(const int* __restrict__ idx,
                                                  const float* __restrict__ WkF,
                                                  const float* __restrict__ WkB,
                                                  const float* __restrict__ bF,
                                                  const float* __restrict__ bB,
                                                  const float* __restrict__ emb) {
    const int dir = blockIdx.z;
    const float* __restrict__ Wk   = dir ? WkB : WkF;
    const float* __restrict__ bias = dir ? bB  : bF;
    const int m0 = blockIdx.x * 128;
    const int n0 = blockIdx.y * 64;
    const int tid = threadIdx.x;

    __shared__ ULL A_s[2][128][9];
    __shared__ ULL B_s[2][64][9];
    __shared__ int row_s[128];

    if (tid < 128) row_s[tid] = idx[m0 + tid];
    __syncthreads();

    const int mt = tid >> 4;
    const int nt = tid & 15;

    ULL acc[8][4];
#pragma unroll
    for (int i = 0; i < 8; i++)
#pragma unroll
        for (int j = 0; j < 4; j++) acc[i][j] = 0ULL;

    ULL aReg[4];
    ULL bReg[2];

    auto grab = [&](int kt) {
#pragma unroll
        for (int l = 0; l < 4; l++) {
            int id = tid + 256 * l;
            int m  = id >> 3;
            int kp = id & 7;
            int k0 = kt * 16 + kp * 2;
            if (k0 < D_) {
                const float* ep = emb + (size_t)row_s[m] * D_ + k0;
                float2 v = *(const float2*)ep;
                aReg[l] = pack2(v.x, v.y);
            } else aReg[l] = 0ULL;
        }
#pragma unroll
        for (int l = 0; l < 2; l++) {
            int id = tid + 256 * l;
            int n  = id & 63;
            int kp = id >> 6;
            int k0 = kt * 16 + kp * 2;
            int gn = n0 + n;
            if (k0 < D_ && gn < NG_) {
                float v0 = Wk[(size_t)k0 * NG_ + gn];
                float v1 = Wk[(size_t)(k0 + 1) * NG_ + gn];
                bReg[l] = pack2(v0, v1);
            } else bReg[l] = 0ULL;
        }
    };
    auto commit = [&](int st) {
#pragma unroll
        for (int l = 0; l < 4; l++) {
            int id = tid + 256 * l;
            A_s[st][id >> 3][id & 7] = aReg[l];
        }
#pragma unroll
        for (int l = 0; l < 2; l++) {
            int id = tid + 256 * l;
            B_s[st][id & 63][id >> 6] = bReg[l];
        }
    };

    grab(0); commit(0);
    __syncthreads();

    for (int kt = 0; kt < GKT; kt++) {
        const int st = kt & 1;
        if (kt + 1 < GKT) grab(kt + 1);

#pragma unroll
        for (int kp = 0; kp < 8; kp++) {
            ULL a2[8], b2[4];
#pragma unroll
            for (int i = 0; i < 8; i++) a2[i] = A_s[st][mt + 16 * i][kp];
#pragma unroll
            for (int j = 0; j < 4; j++) b2[j] = B_s[st][nt + 16 * j][kp];
#pragma unroll
            for (int i = 0; i < 8; i++)
#pragma unroll
                for (int j = 0; j < 4; j++) ffma2(acc[i][j], a2[i], b2[j]);
        }

        if (kt + 1 < GKT) commit((kt + 1) & 1);
        __syncthreads();
    }

#pragma unroll
    for (int i = 0; i < 8; i++) {
        int m = m0 + mt + 16 * i;
        float* orow = &g_zx[dir][m][0];
#pragma unroll
        for (int j = 0; j < 4; j++) {
            int n = n0 + nt + 16 * j;
            if (n < NG_) {
                float2 p = unpack2(acc[i][j]);
                orow[n] = p.x + p.y + bias[n];
            }
        }
    }
}

// ------------------- kernel 2: clustered persistent LSTM -------------------
// 128 CTAs = 16 clusters of 8. Cluster = (dir, batch-group of 4).
// Each CTA: 38 units x 4 batches. Wr slice in regs (k-paired f32x2, 1 col/thread).
// h exchanged by DSMEM push into parity-double-buffered smem; 1 cluster.sync/step.
__global__ void __launch_bounds__(RTc, 1) __cluster_dims__(CL, 1, 1)
lstm_recur(const float* __restrict__ WrF,
           const float* __restrict__ WrB,
           const int* __restrict__ seqlen) {
    const int bx  = blockIdx.x;          // 0..127
    const int dir = bx >> 6;
    const int bg  = (bx >> 3) & 7;       // 0..7, 4 batches each
    const int ug  = bx & 7;              // 0..7 (cluster rank)
    const float* __restrict__ Wr = dir ? WrB : WrF;
    const int u0  = ug * NUc;
    const int tid = threadIdx.x;

    __shared__ ULL   hh[2][BGc][156];                // h as k-pairs, 152 used + pad
    __shared__ float red_s[KCHc][BGc][NCOLc];        // 12160 B
    __shared__ float c_s[BGc][NUc], h_s[BGc][NUc];
    __shared__ int   seq_s[BGc];

    const int  kch = tid / NCOLc;        // 0..4 valid
    const int  c   = tid % NCOLc;        // column within CTA slice
    const bool mm  = (tid < KCHc * NCOLc);   // 760 matmul threads

    const bool gt  = (tid < BGc * NUc);      // 152 gate threads
    const int  gb_ = tid / NUc, gi_ = tid % NUc;
    const int  gu  = u0 + gi_;
    const bool gv  = gt && (gu < U_);

    // ---- preload Wr column slice: w2[j] = (Wr[k0+2j][gc], Wr[k0+2j+1][gc]) ----
    ULL w2[30];
    if (mm) {
        int g = c / NUc, i = c % NUc;
        int u = u0 + i;
        bool v = (u < U_);
        int gc = g * U_ + (v ? u : 0);
        int k0 = kch * KCc;
#pragma unroll
        for (int j = 0; j < 30; j++) {
            float a = 0.f, b = 0.f;
            if (v) {
                a = Wr[(size_t)(k0 + 2 * j)     * NG_ + gc];
                b = Wr[(size_t)(k0 + 2 * j + 1) * NG_ + gc];
            }
            w2[j] = pack2(a, b);
        }
    }
    if (tid < BGc) seq_s[tid] = seqlen[bg * BGc + tid];
    for (int x = tid; x < 2 * BGc * 156; x += RTc) ((ULL*)hh)[x] = 0ULL;
    if (gt) { c_s[gb_][gi_] = 0.f; h_s[gb_][gi_] = 0.f; }
    __syncthreads();
    cluster_sync_();   // all CTAs' hh init done before any remote write

    // local smem slot address of this gate thread's h value (parity 0)
    uint32_t slotA = 0;
    if (gv) slotA = smem_u32(&hh[0][gb_][gu >> 1]) + (gu & 1) * 4;
    const uint32_t parStride = (uint32_t)(BGc * 156 * 8);   // 4992 B

    for (int s = 0; s < T_; s++) {
        const int t = dir ? (T_ - 1 - s) : s;
        const int p = s & 1;

        // ---- prefetch zx row for this step (latency hidden by matmul) ----
        float zpre[4];
        if (gv) {
            const float* zrow = &g_zx[dir][(bg * BGc + gb_) * T_ + t][0];
#pragma unroll
            for (int g = 0; g < 4; g++) zpre[g] = __ldcg(zrow + g * U_ + gu);
        }

        // ---- matmul: partial z for this (kch, col) over 4 batches ----
        if (mm) {
#pragma unroll
            for (int b = 0; b < BGc; b++) {
                const ulonglong2* hp = (const ulonglong2*)&hh[p][b][kch * 30];
                ULL acc = 0ULL;
#pragma unroll
                for (int jj = 0; jj < 15; jj++) {
                    ulonglong2 h2 = hp[jj];
                    ffma2(acc, w2[2 * jj],     h2.x);
                    ffma2(acc, w2[2 * jj + 1], h2.y);
                }
                float2 pr = unpack2(acc);
                red_s[kch][b][c] = pr.x + pr.y;
            }
        }
        __syncthreads();

        // ---- reduce + gates + state update + DSMEM h push ----
        if (gv) {
            float z[4];
#pragma unroll
            for (int g = 0; g < 4; g++) {
                float sum = zpre[g];
#pragma unroll
                for (int k = 0; k < KCHc; k++) sum += red_s[k][gb_][g * NUc + gi_];
                z[g] = sum;
            }
            float ig = sigm(z[0]), fg = sigm(z[1]);
            float gg = tanhf(z[2]), og = sigm(z[3]);
            float c_old = c_s[gb_][gi_], h_old = h_s[gb_][gi_];
            float c_new = fg * c_old + ig * gg;
            float h_new = og * tanhf(c_new);
            bool  mk = (t < seq_s[gb_]);
            float hw = mk ? h_new : h_old;
            float cw = mk ? c_new : c_old;
            c_s[gb_][gi_] = cw;
            h_s[gb_][gi_] = hw;
            g_hs[dir][bg * BGc + gb_][t][gu] = hw;   // history for fc

            // push new h into all 8 cluster CTAs' next-parity buffer
            uint32_t a0 = slotA + (uint32_t)(p ^ 1) * parStride;
#pragma unroll
            for (int r = 0; r < CL; r++) st_cluster_f32(a0, r, hw);
        }

        cluster_sync_();   // orders pushes; releases next step for all CTAs
    }
}

// ------------------- kernel 3: out = [h_fwd|h_bwd] @ fc_W + fc_b -----------
__global__ void __launch_bounds__(256) fc_kernel(const float* __restrict__ fcW,
                                                 const float* __restrict__ fcb,
                                                 float* __restrict__ out) {
    __shared__ float Ws[1803];
    const int tid = threadIdx.x;
    for (int x = tid; x < 1800; x += 256) Ws[x] = fcW[x];
    if (tid < 3) Ws[1800 + tid] = fcb[tid];
    __syncthreads();

    const int wid = tid >> 5, lane = tid & 31;
    const int r = blockIdx.x * 8 + wid;       // 0..16383
    const int b = r >> 9, t = r & 511;
    float a0 = 0.f, a1 = 0.f, a2 = 0.f;
    const float* hf = &g_hs[0][b][t][0];
    const float* hb = &g_hs[1][b][t][0];
    for (int k = lane; k < U_; k += 32) {
        float v = hf[k];
        a0 += v * Ws[k * 3];  a1 += v * Ws[k * 3 + 1];  a2 += v * Ws[k * 3 + 2];
        float w = hb[k];
        a0 += w * Ws[(U_ + k) * 3];  a1 += w * Ws[(U_ + k) * 3 + 1];  a2 += w * Ws[(U_ + k) * 3 + 2];
    }
#pragma unroll
    for (int off = 16; off; off >>= 1) {
        a0 += __shfl_down_sync(0xffffffffu, a0, off);
        a1 += __shfl_down_sync(0xffffffffu, a1, off);
        a2 += __shfl_down_sync(0xffffffffu, a2, off);
    }
    if (lane == 0) {
        out[r * 3 + 0] = a0 + Ws[1800];
        out[r * 3 + 1] = a1 + Ws[1801];
        out[r * 3 + 2] = a2 + Ws[1802];
    }
}

// ------------------- launch ------------------------------------------------
extern "C" void kernel_launch(void* const* d_in, const int* in_sizes, int n_in,
                              void* d_out, int out_size) {
    const int*   inputs = (const int*)d_in[0];
    const int*   seqlen = (const int*)d_in[1];
    const float* emb    = (const float*)d_in[2];
    const float* Wk_f   = (const float*)d_in[3];
    const float* Wr_f   = (const float*)d_in[4];
    const float* b_f    = (const float*)d_in[5];
    const float* Wk_b   = (const float*)d_in[6];
    const float* Wr_b   = (const float*)d_in[7];
    const float* b_b    = (const float*)d_in[8];
    const float* fc_W   = (const float*)d_in[9];
    const float* fc_b   = (const float*)d_in[10];
    float* out = (float*)d_out;

    gemm_zx<<<dim3(128, 19, 2), 256>>>(inputs, Wk_f, Wk_b, b_f, b_b, emb);
    lstm_recur<<<128, RTc>>>(Wr_f, Wr_b, seqlen);
    fc_kernel<<<2048, 256>>>(fc_W, fc_b, out);
}

// round 9
// speedup vs baseline: 1.1200x; 1.1200x over previous
#include <cuda_runtime.h>
#include <cuda_bf16.h>
#include <cstdint>
#include <math.h>

#define B_    32
#define T_    512
#define D_    300
#define U_    300
#define NG_   1200       // 4*U
#define ZPAD  1216       // padded zx row stride
#define M_    16384      // B*T

// ---- clustered recurrence tiling ----
#define CL    8          // CTAs per cluster (unit groups)
#define NUc   38         // units per CTA (8*38=304, last 4 masked)
#define NCOLc 152        // 4*NUc gate columns per CTA
#define BGc   4          // batches per CTA
#define KCHc  4          // k chunks
#define KPc   38         // k-pairs per chunk (4*76 = 304 padded k)
#define HPAD  154        // hh row length in ULL pairs (152 used + pad)
#define RTc   608        // threads = KCHc * NCOLc exactly

typedef unsigned long long ULL;

// ------------------- static device scratch (no allocs allowed) -------------
__device__ __align__(16) float g_zx[2][M_][ZPAD];     // x@Wk+b per dir
__device__ __align__(16) float g_hs[2][B_][T_][U_];   // h history per dir

// ------------------- helpers ----------------------------------------------
union UF2 { float2 f; ULL u; };
__device__ __forceinline__ ULL pack2(float a, float b) {
    UF2 x; x.f = make_float2(a, b); return x.u;
}
__device__ __forceinline__ float2 unpack2(ULL v) {
    UF2 x; x.u = v; return x.f;
}
__device__ __forceinline__ void ffma2(ULL& d, ULL a, ULL b) {
    asm("fma.rn.f32x2 %0, %1, %2, %0;" : "+l"(d) : "l"(a), "l"(b));
}
__device__ __forceinline__ float sigm_f(float x) {
    return __fdividef(1.f, 1.f + __expf(-x));
}
__device__ __forceinline__ float tanh_f(float x) {
    // saturation-safe fast tanh: e=inf -> 2/(e+1)=0 -> +/-1
    float e = __expf(2.f * fabsf(x));
    float t = 1.f - __fdividef(2.f, e + 1.f);
    return copysignf(t, x);
}
__device__ __forceinline__ uint32_t smem_u32(const void* p) {
    uint32_t a;
    asm("{ .reg .u64 t; cvta.to.shared.u64 t, %1; cvt.u32.u64 %0, t; }" : "=r"(a) : "l"(p));
    return a;
}
__device__ __forceinline__ void st_cluster_f32(uint32_t laddr, int rank, float v) {
    uint32_t ra;
    asm volatile("mapa.shared::cluster.u32 %0, %1, %2;" : "=r"(ra) : "r"(laddr), "r"(rank));
    asm volatile("st.shared::cluster.f32 [%0], %1;" :: "r"(ra), "f"(v) : "memory");
}
__device__ __forceinline__ void cluster_sync_() {
    asm volatile("barrier.cluster.arrive.aligned;" ::: "memory");
    asm volatile("barrier.cluster.wait.aligned;" ::: "memory");
}

// ------------------- kernel 1: zx = gather(emb) @ Wk + b -------------------
// (unchanged: 590us, fma 53%) BM=128, BN=64, BK=16, 256 thr, f32x2 k-pairs.
#define GKT 19   // ceil(304/16)

__global__ void __launch_bounds__(256, 2) gemm_zx(const int* __restrict__ idx,
                                                  const float* __restrict__ WkF,
                                                  const float* __restrict__ WkB,
                                                  const float* __restrict__ bF,
                                                  const float* __restrict__ bB,
                                                  const float* __restrict__ emb) {
    const int dir = blockIdx.z;
    const float* __restrict__ Wk   = dir ? WkB : WkF;
    const float* __restrict__ bias = dir ? bB  : bF;
    const int m0 = blockIdx.x * 128;
    const int n0 = blockIdx.y * 64;
    const int tid = threadIdx.x;

    __shared__ ULL A_s[2][128][9];
    __shared__ ULL B_s[2][64][9];
    __shared__ int row_s[128];

    if (tid < 128) row_s[tid] = idx[m0 + tid];
    __syncthreads();

    const int mt = tid >> 4;
    const int nt = tid & 15;

    ULL acc[8][4];
#pragma unroll
    for (int i = 0; i < 8; i++)
#pragma unroll
        for (int j = 0; j < 4; j++) acc[i][j] = 0ULL;

    ULL aReg[4];
    ULL bReg[2];

    auto grab = [&](int kt) {
#pragma unroll
        for (int l = 0; l < 4; l++) {
            int id = tid + 256 * l;
            int m  = id >> 3;
            int kp = id & 7;
            int k0 = kt * 16 + kp * 2;
            if (k0 < D_) {
                const float* ep = emb + (size_t)row_s[m] * D_ + k0;
                float2 v = *(const float2*)ep;
                aReg[l] = pack2(v.x, v.y);
            } else aReg[l] = 0ULL;
        }
#pragma unroll
        for (int l = 0; l < 2; l++) {
            int id = tid + 256 * l;
            int n  = id & 63;
            int kp = id >> 6;
            int k0 = kt * 16 + kp * 2;
            int gn = n0 + n;
            if (k0 < D_ && gn < NG_) {
                float v0 = Wk[(size_t)k0 * NG_ + gn];
                float v1 = Wk[(size_t)(k0 + 1) * NG_ + gn];
                bReg[l] = pack2(v0, v1);
            } else bReg[l] = 0ULL;
        }
    };
    auto commit = [&](int st) {
#pragma unroll
        for (int l = 0; l < 4; l++) {
            int id = tid + 256 * l;
            A_s[st][id >> 3][id & 7] = aReg[l];
        }
#pragma unroll
        for (int l = 0; l < 2; l++) {
            int id = tid + 256 * l;
            B_s[st][id & 63][id >> 6] = bReg[l];
        }
    };

    grab(0); commit(0);
    __syncthreads();

    for (int kt = 0; kt < GKT; kt++) {
        const int st = kt & 1;
        if (kt + 1 < GKT) grab(kt + 1);

#pragma unroll
        for (int kp = 0; kp < 8; kp++) {
            ULL a2[8], b2[4];
#pragma unroll
            for (int i = 0; i < 8; i++) a2[i] = A_s[st][mt + 16 * i][kp];
#pragma unroll
            for (int j = 0; j < 4; j++) b2[j] = B_s[st][nt + 16 * j][kp];
#pragma unroll
            for (int i = 0; i < 8; i++)
#pragma unroll
                for (int j = 0; j < 4; j++) ffma2(acc[i][j], a2[i], b2[j]);
        }

        if (kt + 1 < GKT) commit((kt + 1) & 1);
        __syncthreads();
    }

#pragma unroll
    for (int i = 0; i < 8; i++) {
        int m = m0 + mt + 16 * i;
        float* orow = &g_zx[dir][m][0];
#pragma unroll
        for (int j = 0; j < 4; j++) {
            int n = n0 + nt + 16 * j;
            if (n < NG_) {
                float2 p = unpack2(acc[i][j]);
                orow[n] = p.x + p.y + bias[n];
            }
        }
    }
}

// ------------------- kernel 2: clustered persistent LSTM (spill-free) ------
// 128 CTAs = 16 clusters of 8. Cluster = (dir, batch-group of 4).
// CTA: 38 units x 4 batches. 608 threads = 4 k-chunks x 152 cols.
// Wr slice in regs: w2[38] = 76 regs/thread (fits 107-reg budget -> no spills).
// h exchanged by DSMEM push into parity-double-buffered smem; 1 cluster.sync/step.
__global__ void __launch_bounds__(RTc, 1) __cluster_dims__(CL, 1, 1)
lstm_recur(const float* __restrict__ WrF,
           const float* __restrict__ WrB,
           const int* __restrict__ seqlen) {
    const int bx  = blockIdx.x;          // 0..127
    const int dir = bx >> 6;
    const int bg  = (bx >> 3) & 7;       // 0..7 (4 batches each)
    const int ug  = bx & 7;              // cluster rank
    const float* __restrict__ Wr = dir ? WrB : WrF;
    const int u0  = ug * NUc;
    const int tid = threadIdx.x;

    __shared__ ULL   hh[2][BGc][HPAD];               // h k-pairs: [parity][b][pair]
    __shared__ float red_s[KCHc][BGc][NCOLc];        // 9728 B
    __shared__ float c_s[BGc][NUc], h_s[BGc][NUc];
    __shared__ int   seq_s[BGc];

    const int kch = tid / NCOLc;         // 0..3
    const int c   = tid % NCOLc;         // 0..151

    const bool gt  = (tid < BGc * NUc);  // 152 gate threads
    const int  gb_ = tid / NUc, gi_ = tid % NUc;
    const int  gu  = u0 + gi_;
    const bool gv  = gt && (gu < U_);

    // ---- preload Wr slice: w2[j] = (Wr[k0+2j][gc], Wr[k0+2j+1][gc]) ----
    ULL w2[KPc];
    {
        int g = c / NUc, i = c % NUc;
        int u = u0 + i;
        bool v = (u < U_);
        int gc = g * U_ + (v ? u : 0);
        int k0 = kch * (2 * KPc);
#pragma unroll
        for (int j = 0; j < KPc; j++) {
            int k = k0 + 2 * j;
            float a = (v && k     < D_) ? Wr[(size_t)k       * NG_ + gc] : 0.f;
            float b = (v && k + 1 < D_) ? Wr[(size_t)(k + 1) * NG_ + gc] : 0.f;
            w2[j] = pack2(a, b);
        }
    }
    if (tid < BGc) seq_s[tid] = seqlen[bg * BGc + tid];
    for (int x = tid; x < 2 * BGc * HPAD; x += RTc) ((ULL*)hh)[x] = 0ULL;
    if (gt) { c_s[gb_][gi_] = 0.f; h_s[gb_][gi_] = 0.f; }
    __syncthreads();
    cluster_sync_();   // all CTAs' hh init done before any remote write

    uint32_t slotA = 0;
    if (gv) slotA = smem_u32(&hh[0][gb_][gu >> 1]) + (gu & 1) * 4;
    const uint32_t parStride = (uint32_t)(BGc * HPAD * 8);

    for (int s = 0; s < T_; s++) {
        const int t = dir ? (T_ - 1 - s) : s;
        const int p = s & 1;

        // ---- prefetch zx row for this step (latency hidden by matmul) ----
        float zpre[4];
        if (gv) {
            const float* zrow = &g_zx[dir][(bg * BGc + gb_) * T_ + t][0];
#pragma unroll
            for (int g = 0; g < 4; g++) zpre[g] = __ldcg(zrow + g * U_ + gu);
        }

        // ---- matmul: partial z for (kch, col) over 4 batches ----
#pragma unroll
        for (int b = 0; b < BGc; b++) {
            const ulonglong2* hp = (const ulonglong2*)&hh[p][b][kch * KPc];
            ULL acc = 0ULL;
#pragma unroll
            for (int jj = 0; jj < KPc / 2; jj++) {
                ulonglong2 h2 = hp[jj];
                ffma2(acc, w2[2 * jj],     h2.x);
                ffma2(acc, w2[2 * jj + 1], h2.y);
            }
            float2 pr = unpack2(acc);
            red_s[kch][b][c] = pr.x + pr.y;
        }
        __syncthreads();

        // ---- reduce + gates + state update + DSMEM h push ----
        if (gv) {
            float z[4];
#pragma unroll
            for (int g = 0; g < 4; g++) {
                float sum = zpre[g];
#pragma unroll
                for (int k = 0; k < KCHc; k++) sum += red_s[k][gb_][g * NUc + gi_];
                z[g] = sum;
            }
            float ig = sigm_f(z[0]), fg = sigm_f(z[1]);
            float gg = tanh_f(z[2]), og = sigm_f(z[3]);
            float c_old = c_s[gb_][gi_], h_old = h_s[gb_][gi_];
            float c_new = fg * c_old + ig * gg;
            float h_new = og * tanh_f(c_new);
            bool  mk = (t < seq_s[gb_]);
            float hw = mk ? h_new : h_old;
            float cw = mk ? c_new : c_old;
            c_s[gb_][gi_] = cw;
            h_s[gb_][gi_] = hw;
            g_hs[dir][bg * BGc + gb_][t][gu] = hw;   // history for fc

            // push new h into all 8 cluster CTAs' next-parity buffer
            uint32_t a0 = slotA + (uint32_t)(p ^ 1) * parStride;
#pragma unroll
            for (int r = 0; r < CL; r++) st_cluster_f32(a0, r, hw);
        }

        cluster_sync_();   // orders pushes; releases next step for all CTAs
    }
}

// ------------------- kernel 3: out = [h_fwd|h_bwd] @ fc_W + fc_b -----------
__global__ void __launch_bounds__(256) fc_kernel(const float* __restrict__ fcW,
                                                 const float* __restrict__ fcb,
                                                 float* __restrict__ out) {
    __shared__ float Ws[1803];
    const int tid = threadIdx.x;
    for (int x = tid; x < 1800; x += 256) Ws[x] = fcW[x];
    if (tid < 3) Ws[1800 + tid] = fcb[tid];
    __syncthreads();

    const int wid = tid >> 5, lane = tid & 31;
    const int r = blockIdx.x * 8 + wid;       // 0..16383
    const int b = r >> 9, t = r & 511;
    float a0 = 0.f, a1 = 0.f, a2 = 0.f;
    const float* hf = &g_hs[0][b][t][0];
    const float* hb = &g_hs[1][b][t][0];
    for (int k = lane; k < U_; k += 32) {
        float v = hf[k];
        a0 += v * Ws[k * 3];  a1 += v * Ws[k * 3 + 1];  a2 += v * Ws[k * 3 + 2];
        float w = hb[k];
        a0 += w * Ws[(U_ + k) * 3];  a1 += w * Ws[(U_ + k) * 3 + 1];  a2 += w * Ws[(U_ + k) * 3 + 2];
    }
#pragma unroll
    for (int off = 16; off; off >>= 1) {
        a0 += __shfl_down_sync(0xffffffffu, a0, off);
        a1 += __shfl_down_sync(0xffffffffu, a1, off);
        a2 += __shfl_down_sync(0xffffffffu, a2, off);
    }
    if (lane == 0) {
        out[r * 3 + 0] = a0 + Ws[1800];
        out[r * 3 + 1] = a1 + Ws[1801];
        out[r * 3 + 2] = a2 + Ws[1802];
    }
}

// ------------------- launch ------------------------------------------------
extern "C" void kernel_launch(void* const* d_in, const int* in_sizes, int n_in,
                              void* d_out, int out_size) {
    const int*   inputs = (const int*)d_in[0];
    const int*   seqlen = (const int*)d_in[1];
    const float* emb    = (const float*)d_in[2];
    const float* Wk_f   = (const float*)d_in[3];
    const float* Wr_f   = (const float*)d_in[4];
    const float* b_f    = (const float*)d_in[5];
    const float* Wk_b   = (const float*)d_in[6];
    const float* Wr_b   = (const float*)d_in[7];
    const float* b_b    = (const float*)d_in[8];
    const float* fc_W   = (const float*)d_in[9];
    const float* fc_b   = (const float*)d_in[10];
    float* out = (float*)d_out;

    gemm_zx<<<dim3(128, 19, 2), 256>>>(inputs, Wk_f, Wk_b, b_f, b_b, emb);
    lstm_recur<<<128, RTc>>>(Wr_f, Wr_b, seqlen);
    fc_kernel<<<2048, 256>>>(fc_W, fc_b, out);
}